// round 6
// baseline (speedup 1.0000x reference)
#include <cuda_runtime.h>
#include <cuda_fp16.h>
#include <cstdint>

// Problem constants
#define BN_TOTAL 16384      // B*N = 4*4096
#define OUT1_OFF 1048576    // B*N*1*64
#define OUT2_OFF 4194304    // OUT1_OFF + B*N*3*64

// Scratch (device globals — the sanctioned no-alloc scratch mechanism)
__device__ __align__(16) float  g_Mv[3 * 64 * 64];
__device__ __align__(16) __half g_xvh[BN_TOTAL * 9 * 64];   // fp16 gathered tensor
__device__ __align__(16) float  g_skip[BN_TOTAL * 9 * 64];  // fp32 skip path

__device__ __forceinline__ void ffma2(unsigned long long &d, unsigned long long a, unsigned long long b) {
    asm("fma.rn.f32x2 %0, %1, %2, %3;" : "=l"(d) : "l"(a), "l"(b), "l"(d));
}
__device__ __forceinline__ float2 unpk(unsigned long long v) {
    float2 f;
    asm("mov.b64 {%0, %1}, %2;" : "=f"(f.x), "=f"(f.y) : "l"(v));
    return f;
}

// ---------------------------------------------------------------------------
// Kernel M: Mv_d = Wconv_d @ Wv_d.  12 blocks = 3 degrees x 4 col-slices(16).
// ---------------------------------------------------------------------------
__global__ __launch_bounds__(256) void kernelM(
    const float* __restrict__ Wc0, const float* __restrict__ Wc1,
    const float* __restrict__ Wc2, const float* __restrict__ Wv0,
    const float* __restrict__ Wv1, const float* __restrict__ Wv2)
{
    __shared__ float sWc[64 * 65];
    __shared__ __align__(16) float sWvS[64 * 16];
    int d = blockIdx.x >> 2, sl = blockIdx.x & 3;
    int g0 = sl * 16;
    const float* Wc = (d == 0) ? Wc0 : (d == 1 ? Wc1 : Wc2);
    const float* Wv = (d == 0) ? Wv0 : (d == 1 ? Wv1 : Wv2);
    int tid = threadIdx.x;

    #pragma unroll
    for (int it = 0; it < 16; ++it) {
        int i = tid + it * 256;
        int k = i & 63, c = i >> 6;
        sWc[c * 65 + k] = Wc[i];
    }
    {
        int i = tid * 4;
        int k = i >> 4, cc = i & 15;
        *(float4*)(sWvS + k * 16 + cc) = *(const float4*)(Wv + k * 64 + g0 + cc);
    }
    __syncthreads();

    int c = tid & 63, cg = (tid >> 6) * 4;
    float4 acc = make_float4(0.f, 0.f, 0.f, 0.f);
    #pragma unroll 8
    for (int k = 0; k < 64; ++k) {
        float a = sWc[c * 65 + k];
        float4 b = *(const float4*)(sWvS + k * 16 + cg);
        acc.x = fmaf(a, b.x, acc.x);
        acc.y = fmaf(a, b.y, acc.y);
        acc.z = fmaf(a, b.z, acc.z);
        acc.w = fmaf(a, b.w, acc.w);
    }
    *(float4*)(g_Mv + d * 4096 + c * 64 + g0 + cg) = acc;
}

// ---------------------------------------------------------------------------
// Kernel A: fused dual GEMM per 64-row tile, warp-uniform column mapping.
//   Warp w owns cols 8w..8w+7 (both matrices); lanes span rows (2 rows/lane).
//   -> every b LDS.128 is an all-lanes broadcast: crossbar traffic /4.8,
//      kernel becomes FFMA2-issue bound (~33us floor).
// Dynamic smem: sX(64x68) + sWmT(64x68) + sWsT(64x68) = 52224 B.
// ---------------------------------------------------------------------------
#define ASTR 68
__global__ __launch_bounds__(256) void kernelA(
    const float* __restrict__ x0, const float* __restrict__ x1, const float* __restrict__ x2,
    const float* __restrict__ mask,
    const float* __restrict__ Ws0, const float* __restrict__ Ws1, const float* __restrict__ Ws2)
{
    extern __shared__ __align__(16) float smem[];
    float* sX   = smem;                 // [64][ASTR] row r, col k
    float* sWmT = smem + 64 * ASTR;     // [64][ASTR] row c, col k (transposed)
    float* sWsT = smem + 2 * 64 * ASTR;

    int bx = blockIdx.x, tid = threadIdx.x;
    int tile, md, moff;
    const float *x, *Ws, *Wm;
    if (bx < 256)       { tile = bx;        x = x0; Ws = Ws0; Wm = g_Mv;        md = 1; moff = 0; }
    else if (bx < 1024) { tile = bx - 256;  x = x1; Ws = Ws1; Wm = g_Mv + 4096; md = 3; moff = 1; }
    else                { tile = bx - 1024; x = x2; Ws = Ws2; Wm = g_Mv + 8192; md = 5; moff = 4; }
    int row0 = tile * 64;

    // x tile with mask applied
    const float* xb = x + (size_t)row0 * 64;
    #pragma unroll
    for (int it = 0; it < 4; ++it) {
        int i = tid * 4 + it * 1024;
        int r = i >> 6, c = i & 63;
        float4 v = *(const float4*)(xb + i);
        float mk = mask[(row0 + r) / md];
        float* dst = sX + r * ASTR + c;
        dst[0] = v.x * mk; dst[1] = v.y * mk; dst[2] = v.z * mk; dst[3] = v.w * mk;
    }
    // Transposed weight loads
    #pragma unroll
    for (int it = 0; it < 16; ++it) {
        int i = tid + it * 256;
        int k = i >> 6, c = i & 63;
        sWmT[c * ASTR + k] = Wm[i];
        sWsT[c * ASTR + k] = Ws[i];
    }
    __syncthreads();

    int wp = tid >> 5, lane = tid & 31;
    int c0 = wp * 8;

    unsigned long long accM[2][8], accS[2][8];
    #pragma unroll
    for (int ri = 0; ri < 2; ri++)
        #pragma unroll
        for (int j = 0; j < 8; j++) { accM[ri][j] = 0ull; accS[ri][j] = 0ull; }

    #pragma unroll 2
    for (int kc = 0; kc < 64; kc += 4) {
        ulonglong2 a0 = *(const ulonglong2*)(sX + lane * ASTR + kc);
        ulonglong2 a1 = *(const ulonglong2*)(sX + (lane + 32) * ASTR + kc);
        #pragma unroll
        for (int j = 0; j < 8; ++j) {
            ulonglong2 bm = *(const ulonglong2*)(sWmT + (c0 + j) * ASTR + kc);  // broadcast
            ulonglong2 bs = *(const ulonglong2*)(sWsT + (c0 + j) * ASTR + kc);  // broadcast
            ffma2(accM[0][j], a0.x, bm.x); ffma2(accM[0][j], a0.y, bm.y);
            ffma2(accM[1][j], a1.x, bm.x); ffma2(accM[1][j], a1.y, bm.y);
            ffma2(accS[0][j], a0.x, bs.x); ffma2(accS[0][j], a0.y, bs.y);
            ffma2(accS[1][j], a1.x, bs.x); ffma2(accS[1][j], a1.y, bs.y);
        }
    }

    // Epilogue: reduce pair halves, store fp16 xv (16B) + fp32 skip (32B) per row
    #pragma unroll
    for (int ri = 0; ri < 2; ++ri) {
        int r = row0 + lane + 32 * ri;
        int bn = r / md, mloc = r - bn * md;
        int base = (bn * 9 + moff + mloc) * 64 + c0;
        float ms[8], ss[8];
        #pragma unroll
        for (int j = 0; j < 8; ++j) {
            float2 mm = unpk(accM[ri][j]); ms[j] = mm.x + mm.y;
            float2 sv = unpk(accS[ri][j]); ss[j] = sv.x + sv.y;
        }
        __half2 h[4];
        #pragma unroll
        for (int j = 0; j < 4; ++j) h[j] = __floats2half2_rn(ms[2 * j], ms[2 * j + 1]);
        *(uint4*)(g_xvh + base) = *(uint4*)h;
        *(float4*)(g_skip + base)     = make_float4(ss[0], ss[1], ss[2], ss[3]);
        *(float4*)(g_skip + base + 4) = make_float4(ss[4], ss[5], ss[6], ss[7]);
    }
}

// ---------------------------------------------------------------------------
// Kernel B: one block per point (b,n). 288 threads = 9 warps (one per m-row).
//   Every warp redundantly computes weights + register-compacts (ballot/__fns/
//   shfl) into its warp-private smem slice -> no block barrier before gather.
// ---------------------------------------------------------------------------
__global__ __launch_bounds__(288) void kernelB(
    const float* __restrict__ points, const int* __restrict__ pidx,
    const float* __restrict__ mask, float* __restrict__ out)
{
    __shared__ float swv[9][32];
    __shared__ int   srw[9][32];
    __shared__ __align__(8) float vbuf[576];
    __shared__ __align__(8) float fbuf[192];

    int bn = blockIdx.x;
    int tid = threadIdx.x;
    int m = tid >> 5, lane = tid & 31;

    // Per-warp redundant weight computation + compaction (warp-synchronous)
    int idx  = pidx[bn * 32 + lane];
    int prow = ((bn >> 12) << 12) + idx;
    float cx = points[bn * 3 + 0], cy = points[bn * 3 + 1], cz = points[bn * 3 + 2];
    float dx = points[prow * 3 + 0] - cx;
    float dy = points[prow * 3 + 1] - cy;
    float dz = points[prow * 3 + 2] - cz;
    float r  = sqrtf(fmaf(dx, dx, fmaf(dy, dy, fmaf(dz, dz, 1e-12f))));
    float w  = 1.0f - r * 2.5f;
    unsigned bal = __ballot_sync(0xffffffffu, w > 0.0f);
    int nnz = __popc(bal);
    int src = __fns(bal, 0, lane + 1);          // lane-th set bit (-1 if none)
    float wc = __shfl_sync(0xffffffffu, w, src & 31);
    int   rc = __shfl_sync(0xffffffffu, prow, src & 31) * 576;
    if (lane < nnz) { swv[m][lane] = wc; srw[m][lane] = rc; }
    __syncwarp();

    int off = m * 64 + lane * 2;

    float ax = 0.f, ay = 0.f;
    int i = 0;
    for (; i + 4 <= nnz; i += 4) {
        float w0 = swv[m][i + 0], w1 = swv[m][i + 1], w2 = swv[m][i + 2], w3 = swv[m][i + 3];
        float2 p0 = __half22float2(*(const __half2*)(g_xvh + srw[m][i + 0] + off));
        float2 p1 = __half22float2(*(const __half2*)(g_xvh + srw[m][i + 1] + off));
        float2 p2 = __half22float2(*(const __half2*)(g_xvh + srw[m][i + 2] + off));
        float2 p3 = __half22float2(*(const __half2*)(g_xvh + srw[m][i + 3] + off));
        ax = fmaf(w0, p0.x, ax); ay = fmaf(w0, p0.y, ay);
        ax = fmaf(w1, p1.x, ax); ay = fmaf(w1, p1.y, ay);
        ax = fmaf(w2, p2.x, ax); ay = fmaf(w2, p2.y, ay);
        ax = fmaf(w3, p3.x, ax); ay = fmaf(w3, p3.y, ay);
    }
    for (; i < nnz; ++i) {
        float w0 = swv[m][i];
        float2 p0 = __half22float2(*(const __half2*)(g_xvh + srw[m][i] + off));
        ax = fmaf(w0, p0.x, ax); ay = fmaf(w0, p0.y, ay);
    }
    vbuf[off] = ax; vbuf[off + 1] = ay;
    __syncthreads();

    if (tid < 192) {
        int d  = tid >> 6, co = tid & 63;
        int m0 = (d == 0) ? 0 : (d == 1 ? 1 : 4);
        int mc = (d == 0) ? 1 : (d == 1 ? 3 : 5);
        float S = 0.f;
        for (int mm = 0; mm < mc; ++mm) {
            float v = vbuf[(m0 + mm) * 64 + co];
            S = fmaf(v, v, S);
        }
        float scale = rsqrtf(S + 0.01f);
        float f = scale;
        if (d > 0) {
            float S2 = S * scale * scale;             // = sum of normalized v^2
            float nn = sqrtf(S2 + 0.01f);
            f = scale * (1.0f / (1.0f + __expf(-nn)));
        }
        fbuf[tid] = f;
    }
    __syncthreads();

    float mk = mask[bn];
    int d = (m == 0) ? 0 : (m < 4 ? 1 : 2);
    float2 f2 = *(const float2*)&fbuf[d * 64 + 2 * lane];
    float a0 = ax * f2.x, a1 = ay * f2.y;
    if (m == 0) { a0 = fmaxf(a0, 0.f); a1 = fmaxf(a1, 0.f); }

    float2 sk = *(const float2*)(g_skip + bn * 576 + off);
    float o0 = (a0 + sk.x) * mk;
    float o1 = (a1 + sk.y) * mk;

    float* op;
    if (m == 0)      op = out + bn * 64 + 2 * lane;
    else if (m < 4)  op = out + OUT1_OFF + (bn * 3 + (m - 1)) * 64 + 2 * lane;
    else             op = out + OUT2_OFF + (bn * 5 + (m - 4)) * 64 + 2 * lane;
    *(float2*)op = make_float2(o0, o1);
}

// ---------------------------------------------------------------------------
extern "C" void kernel_launch(void* const* d_in, const int* in_sizes, int n_in,
                              void* d_out, int out_size) {
    const float* x0     = (const float*)d_in[0];
    const float* x1     = (const float*)d_in[1];
    const float* x2     = (const float*)d_in[2];
    const float* points = (const float*)d_in[3];
    const int*   pidx   = (const int*)  d_in[4];
    const float* mask   = (const float*)d_in[5];
    const float* Wc0    = (const float*)d_in[6];
    const float* Wc1    = (const float*)d_in[7];
    const float* Wc2    = (const float*)d_in[8];
    const float* Wv0    = (const float*)d_in[9];
    const float* Wv1    = (const float*)d_in[10];
    const float* Wv2    = (const float*)d_in[11];
    const float* Ws0    = (const float*)d_in[12];
    const float* Ws1    = (const float*)d_in[13];
    const float* Ws2    = (const float*)d_in[14];
    float* out = (float*)d_out;

    const int smemA = 3 * 64 * ASTR * sizeof(float);   // 52224 B
    cudaFuncSetAttribute(kernelA, cudaFuncAttributeMaxDynamicSharedMemorySize, smemA);

    kernelM<<<12, 256>>>(Wc0, Wc1, Wc2, Wv0, Wv1, Wv2);
    kernelA<<<2304, 256, smemA>>>(x0, x1, x2, mask, Ws0, Ws1, Ws2);
    kernelB<<<16384, 288>>>(points, pidx, mask, out);
}

// round 9
// speedup vs baseline: 1.0698x; 1.0698x over previous
// R8 resubmit (v3) of the R6/R7 controlled experiment:
//   kernelA = warp-uniform broadcast dual-GEMM (new variable under test)
//   kernelB = R5 known-good ballot+barrier version
//   kernelM = R5 known-good 12-block version
#include <cuda_runtime.h>
#include <cuda_fp16.h>
#include <cstdint>

// Problem constants
#define BN_TOTAL 16384      // B*N = 4*4096
#define OUT1_OFF 1048576    // B*N*1*64
#define OUT2_OFF 4194304    // OUT1_OFF + B*N*3*64

// Scratch (device globals — the sanctioned no-alloc scratch mechanism)
__device__ __align__(16) float  g_Mv[3 * 64 * 64];
__device__ __align__(16) __half g_xvh[BN_TOTAL * 9 * 64];   // fp16 gathered tensor
__device__ __align__(16) float  g_skip[BN_TOTAL * 9 * 64];  // fp32 skip path

__device__ __forceinline__ void ffma2(unsigned long long &d, unsigned long long a, unsigned long long b) {
    asm("fma.rn.f32x2 %0, %1, %2, %3;" : "=l"(d) : "l"(a), "l"(b), "l"(d));
}
__device__ __forceinline__ float2 unpk(unsigned long long v) {
    float2 f;
    asm("mov.b64 {%0, %1}, %2;" : "=f"(f.x), "=f"(f.y) : "l"(v));
    return f;
}

// ---------------------------------------------------------------------------
// Kernel M: Mv_d = Wconv_d @ Wv_d.  12 blocks = 3 degrees x 4 col-slices(16).
// ---------------------------------------------------------------------------
__global__ __launch_bounds__(256) void kernelM(
    const float* __restrict__ Wc0, const float* __restrict__ Wc1,
    const float* __restrict__ Wc2, const float* __restrict__ Wv0,
    const float* __restrict__ Wv1, const float* __restrict__ Wv2)
{
    __shared__ float sWc[64 * 65];
    __shared__ __align__(16) float sWvS[64 * 16];
    int d = blockIdx.x >> 2, sl = blockIdx.x & 3;
    int g0 = sl * 16;
    const float* Wc = (d == 0) ? Wc0 : (d == 1 ? Wc1 : Wc2);
    const float* Wv = (d == 0) ? Wv0 : (d == 1 ? Wv1 : Wv2);
    int tid = threadIdx.x;

    #pragma unroll
    for (int it = 0; it < 16; ++it) {
        int i = tid + it * 256;
        int k = i & 63, c = i >> 6;
        sWc[c * 65 + k] = Wc[i];
    }
    {
        int i = tid * 4;
        int k = i >> 4, cc = i & 15;
        *(float4*)(sWvS + k * 16 + cc) = *(const float4*)(Wv + k * 64 + g0 + cc);
    }
    __syncthreads();

    int c = tid & 63, cg = (tid >> 6) * 4;
    float4 acc = make_float4(0.f, 0.f, 0.f, 0.f);
    #pragma unroll 8
    for (int k = 0; k < 64; ++k) {
        float a = sWc[c * 65 + k];
        float4 b = *(const float4*)(sWvS + k * 16 + cg);
        acc.x = fmaf(a, b.x, acc.x);
        acc.y = fmaf(a, b.y, acc.y);
        acc.z = fmaf(a, b.z, acc.z);
        acc.w = fmaf(a, b.w, acc.w);
    }
    *(float4*)(g_Mv + d * 4096 + c * 64 + g0 + cg) = acc;
}

// ---------------------------------------------------------------------------
// Kernel A: fused dual GEMM per 64-row tile, warp-uniform column mapping.
//   Warp w owns cols 8w..8w+7 (both matrices); lanes span rows (2 rows/lane).
//   -> every b LDS.128 is an all-lanes broadcast: crossbar/block 786KB->160KB,
//      kernel pinned at the FFMA2 issue floor (~4096 cyc/block).
// Dynamic smem: sX(64x68) + sWmT(64x68) + sWsT(64x68) = 52224 B.
// ---------------------------------------------------------------------------
#define ASTR 68
__global__ __launch_bounds__(256) void kernelA(
    const float* __restrict__ x0, const float* __restrict__ x1, const float* __restrict__ x2,
    const float* __restrict__ mask,
    const float* __restrict__ Ws0, const float* __restrict__ Ws1, const float* __restrict__ Ws2)
{
    extern __shared__ __align__(16) float smem[];
    float* sX   = smem;                 // [64][ASTR] row r, col k
    float* sWmT = smem + 64 * ASTR;     // [64][ASTR] row c, col k (transposed)
    float* sWsT = smem + 2 * 64 * ASTR;

    int bx = blockIdx.x, tid = threadIdx.x;
    int tile, md, moff;
    const float *x, *Ws, *Wm;
    if (bx < 256)       { tile = bx;        x = x0; Ws = Ws0; Wm = g_Mv;        md = 1; moff = 0; }
    else if (bx < 1024) { tile = bx - 256;  x = x1; Ws = Ws1; Wm = g_Mv + 4096; md = 3; moff = 1; }
    else                { tile = bx - 1024; x = x2; Ws = Ws2; Wm = g_Mv + 8192; md = 5; moff = 4; }
    int row0 = tile * 64;

    // x tile with mask applied
    const float* xb = x + (size_t)row0 * 64;
    #pragma unroll
    for (int it = 0; it < 4; ++it) {
        int i = tid * 4 + it * 1024;
        int r = i >> 6, c = i & 63;
        float4 v = *(const float4*)(xb + i);
        float mk = mask[(row0 + r) / md];
        float* dst = sX + r * ASTR + c;
        dst[0] = v.x * mk; dst[1] = v.y * mk; dst[2] = v.z * mk; dst[3] = v.w * mk;
    }
    // Transposed weight loads
    #pragma unroll
    for (int it = 0; it < 16; ++it) {
        int i = tid + it * 256;
        int k = i >> 6, c = i & 63;
        sWmT[c * ASTR + k] = Wm[i];
        sWsT[c * ASTR + k] = Ws[i];
    }
    __syncthreads();

    int wp = tid >> 5, lane = tid & 31;
    int c0 = wp * 8;

    unsigned long long accM[2][8], accS[2][8];
    #pragma unroll
    for (int ri = 0; ri < 2; ri++)
        #pragma unroll
        for (int j = 0; j < 8; j++) { accM[ri][j] = 0ull; accS[ri][j] = 0ull; }

    #pragma unroll 2
    for (int kc = 0; kc < 64; kc += 4) {
        ulonglong2 a0 = *(const ulonglong2*)(sX + lane * ASTR + kc);
        ulonglong2 a1 = *(const ulonglong2*)(sX + (lane + 32) * ASTR + kc);
        #pragma unroll
        for (int j = 0; j < 8; ++j) {
            ulonglong2 bm = *(const ulonglong2*)(sWmT + (c0 + j) * ASTR + kc);  // broadcast
            ulonglong2 bs = *(const ulonglong2*)(sWsT + (c0 + j) * ASTR + kc);  // broadcast
            ffma2(accM[0][j], a0.x, bm.x); ffma2(accM[0][j], a0.y, bm.y);
            ffma2(accM[1][j], a1.x, bm.x); ffma2(accM[1][j], a1.y, bm.y);
            ffma2(accS[0][j], a0.x, bs.x); ffma2(accS[0][j], a0.y, bs.y);
            ffma2(accS[1][j], a1.x, bs.x); ffma2(accS[1][j], a1.y, bs.y);
        }
    }

    // Epilogue: reduce pair halves, store fp16 xv (16B) + fp32 skip (32B) per row
    #pragma unroll
    for (int ri = 0; ri < 2; ++ri) {
        int r = row0 + lane + 32 * ri;
        int bn = r / md, mloc = r - bn * md;
        int base = (bn * 9 + moff + mloc) * 64 + c0;
        float ms[8], ss[8];
        #pragma unroll
        for (int j = 0; j < 8; ++j) {
            float2 mm = unpk(accM[ri][j]); ms[j] = mm.x + mm.y;
            float2 sv = unpk(accS[ri][j]); ss[j] = sv.x + sv.y;
        }
        __half2 h[4];
        #pragma unroll
        for (int j = 0; j < 4; ++j) h[j] = __floats2half2_rn(ms[2 * j], ms[2 * j + 1]);
        *(uint4*)(g_xvh + base) = *(uint4*)h;
        *(float4*)(g_skip + base)     = make_float4(ss[0], ss[1], ss[2], ss[3]);
        *(float4*)(g_skip + base + 4) = make_float4(ss[4], ss[5], ss[6], ss[7]);
    }
}

// ---------------------------------------------------------------------------
// Kernel B (R5 known-good): one block per point, 288 threads.
//   warp 0 computes weights + ballot-compacts; block barrier; 9 warps gather.
// ---------------------------------------------------------------------------
__global__ __launch_bounds__(288) void kernelB(
    const float* __restrict__ points, const int* __restrict__ pidx,
    const float* __restrict__ mask, float* __restrict__ out)
{
    __shared__ float sw[32];
    __shared__ int   srow[32];
    __shared__ int   snnz;
    __shared__ __align__(8) float vbuf[576];
    __shared__ __align__(8) float fbuf[192];

    int bn = blockIdx.x;
    int tid = threadIdx.x;

    if (tid < 32) {
        int idx  = pidx[bn * 32 + tid];
        int b    = bn >> 12;                 // N = 4096
        int prow = (b << 12) + idx;
        float cx = points[bn * 3 + 0], cy = points[bn * 3 + 1], cz = points[bn * 3 + 2];
        float dx = points[prow * 3 + 0] - cx;
        float dy = points[prow * 3 + 1] - cy;
        float dz = points[prow * 3 + 2] - cz;
        float r  = sqrtf(fmaf(dx, dx, fmaf(dy, dy, fmaf(dz, dz, 1e-12f))));
        float w  = 1.0f - r / 0.4f;
        bool act = w > 0.0f;
        unsigned bal = __ballot_sync(0xffffffffu, act);
        int pos = __popc(bal & ((1u << tid) - 1u));
        if (act) { sw[pos] = w; srow[pos] = prow * 576; }
        if (tid == 0) snnz = __popc(bal);
    }
    __syncthreads();

    int m = tid >> 5, j = tid & 31;
    int off = m * 64 + j * 2;
    int nnz = snnz;

    float ax = 0.f, ay = 0.f;
    int i = 0;
    for (; i + 4 <= nnz; i += 4) {
        float w0 = sw[i + 0], w1 = sw[i + 1], w2 = sw[i + 2], w3 = sw[i + 3];
        float2 p0 = __half22float2(*(const __half2*)(g_xvh + srow[i + 0] + off));
        float2 p1 = __half22float2(*(const __half2*)(g_xvh + srow[i + 1] + off));
        float2 p2 = __half22float2(*(const __half2*)(g_xvh + srow[i + 2] + off));
        float2 p3 = __half22float2(*(const __half2*)(g_xvh + srow[i + 3] + off));
        ax = fmaf(w0, p0.x, ax); ay = fmaf(w0, p0.y, ay);
        ax = fmaf(w1, p1.x, ax); ay = fmaf(w1, p1.y, ay);
        ax = fmaf(w2, p2.x, ax); ay = fmaf(w2, p2.y, ay);
        ax = fmaf(w3, p3.x, ax); ay = fmaf(w3, p3.y, ay);
    }
    for (; i < nnz; ++i) {
        float w0 = sw[i];
        float2 p0 = __half22float2(*(const __half2*)(g_xvh + srow[i] + off));
        ax = fmaf(w0, p0.x, ax); ay = fmaf(w0, p0.y, ay);
    }
    vbuf[off] = ax; vbuf[off + 1] = ay;
    __syncthreads();

    if (tid < 192) {
        int d  = tid >> 6, co = tid & 63;
        int m0 = (d == 0) ? 0 : (d == 1 ? 1 : 4);
        int mc = (d == 0) ? 1 : (d == 1 ? 3 : 5);
        float S = 0.f;
        for (int mm = 0; mm < mc; ++mm) {
            float v = vbuf[(m0 + mm) * 64 + co];
            S = fmaf(v, v, S);
        }
        float scale = rsqrtf(S + 0.01f);
        float f = scale;
        if (d > 0) {
            float S2 = S * scale * scale;             // = sum of normalized v^2
            float nn = sqrtf(S2 + 0.01f);
            f = scale * (1.0f / (1.0f + __expf(-nn)));
        }
        fbuf[tid] = f;
    }
    __syncthreads();

    float mk = mask[bn];
    int d = (m == 0) ? 0 : (m < 4 ? 1 : 2);
    float2 f2 = *(const float2*)&fbuf[d * 64 + 2 * j];
    float a0 = ax * f2.x, a1 = ay * f2.y;
    if (m == 0) { a0 = fmaxf(a0, 0.f); a1 = fmaxf(a1, 0.f); }

    float2 sk = *(const float2*)(g_skip + bn * 576 + off);
    float o0 = (a0 + sk.x) * mk;
    float o1 = (a1 + sk.y) * mk;

    float* op;
    if (m == 0)      op = out + bn * 64 + 2 * j;
    else if (m < 4)  op = out + OUT1_OFF + (bn * 3 + (m - 1)) * 64 + 2 * j;
    else             op = out + OUT2_OFF + (bn * 5 + (m - 4)) * 64 + 2 * j;
    *(float2*)op = make_float2(o0, o1);
}

// ---------------------------------------------------------------------------
extern "C" void kernel_launch(void* const* d_in, const int* in_sizes, int n_in,
                              void* d_out, int out_size) {
    const float* x0     = (const float*)d_in[0];
    const float* x1     = (const float*)d_in[1];
    const float* x2     = (const float*)d_in[2];
    const float* points = (const float*)d_in[3];
    const int*   pidx   = (const int*)  d_in[4];
    const float* mask   = (const float*)d_in[5];
    const float* Wc0    = (const float*)d_in[6];
    const float* Wc1    = (const float*)d_in[7];
    const float* Wc2    = (const float*)d_in[8];
    const float* Wv0    = (const float*)d_in[9];
    const float* Wv1    = (const float*)d_in[10];
    const float* Wv2    = (const float*)d_in[11];
    const float* Ws0    = (const float*)d_in[12];
    const float* Ws1    = (const float*)d_in[13];
    const float* Ws2    = (const float*)d_in[14];
    float* out = (float*)d_out;

    const int smemA = 3 * 64 * ASTR * sizeof(float);   // 52224 B
    cudaFuncSetAttribute(kernelA, cudaFuncAttributeMaxDynamicSharedMemorySize, smemA);

    kernelM<<<12, 256>>>(Wc0, Wc1, Wc2, Wv0, Wv1, Wv2);
    kernelA<<<2304, 256, smemA>>>(x0, x1, x2, mask, Ws0, Ws1, Ws2);
    kernelB<<<16384, 288>>>(points, pidx, mask, out);
}

// round 10
// speedup vs baseline: 1.2693x; 1.1865x over previous
// R10: kernelA moved to tensor cores (mma.sync m16n8k8 tf32, 3-term split).
//      kernelB = R5 known-good. kernelM = R5 known-good.
#include <cuda_runtime.h>
#include <cuda_fp16.h>
#include <cstdint>

#define BN_TOTAL 16384      // B*N = 4*4096
#define OUT1_OFF 1048576    // B*N*1*64
#define OUT2_OFF 4194304    // OUT1_OFF + B*N*3*64

__device__ __align__(16) float  g_Mv[3 * 64 * 64];
__device__ __align__(16) __half g_xvh[BN_TOTAL * 9 * 64];   // fp16 gathered tensor
__device__ __align__(16) float  g_skip[BN_TOTAL * 9 * 64];  // fp32 skip path

__device__ __forceinline__ uint32_t f2tf(float x) {
    uint32_t r;
    asm("cvt.rna.tf32.f32 %0, %1;" : "=r"(r) : "f"(x));
    return r;
}
__device__ __forceinline__ float tf2f(uint32_t u) { return __uint_as_float(u); }

#define MMA_TF32(acc, a0, a1, a2, a3, b0, b1)                                   \
    asm volatile(                                                               \
        "mma.sync.aligned.m16n8k8.row.col.f32.tf32.tf32.f32 "                   \
        "{%0,%1,%2,%3}, {%4,%5,%6,%7}, {%8,%9}, {%0,%1,%2,%3};"                 \
        : "+f"((acc)[0]), "+f"((acc)[1]), "+f"((acc)[2]), "+f"((acc)[3])        \
        : "r"(a0), "r"(a1), "r"(a2), "r"(a3), "r"(b0), "r"(b1))

// ---------------------------------------------------------------------------
// Kernel M: Mv_d = Wconv_d @ Wv_d.  12 blocks = 3 degrees x 4 col-slices(16).
// ---------------------------------------------------------------------------
__global__ __launch_bounds__(256) void kernelM(
    const float* __restrict__ Wc0, const float* __restrict__ Wc1,
    const float* __restrict__ Wc2, const float* __restrict__ Wv0,
    const float* __restrict__ Wv1, const float* __restrict__ Wv2)
{
    __shared__ float sWc[64 * 65];
    __shared__ __align__(16) float sWvS[64 * 16];
    int d = blockIdx.x >> 2, sl = blockIdx.x & 3;
    int g0 = sl * 16;
    const float* Wc = (d == 0) ? Wc0 : (d == 1 ? Wc1 : Wc2);
    const float* Wv = (d == 0) ? Wv0 : (d == 1 ? Wv1 : Wv2);
    int tid = threadIdx.x;

    #pragma unroll
    for (int it = 0; it < 16; ++it) {
        int i = tid + it * 256;
        int k = i & 63, c = i >> 6;
        sWc[c * 65 + k] = Wc[i];
    }
    {
        int i = tid * 4;
        int k = i >> 4, cc = i & 15;
        *(float4*)(sWvS + k * 16 + cc) = *(const float4*)(Wv + k * 64 + g0 + cc);
    }
    __syncthreads();

    int c = tid & 63, cg = (tid >> 6) * 4;
    float4 acc = make_float4(0.f, 0.f, 0.f, 0.f);
    #pragma unroll 8
    for (int k = 0; k < 64; ++k) {
        float a = sWc[c * 65 + k];
        float4 b = *(const float4*)(sWvS + k * 16 + cg);
        acc.x = fmaf(a, b.x, acc.x);
        acc.y = fmaf(a, b.y, acc.y);
        acc.z = fmaf(a, b.z, acc.z);
        acc.w = fmaf(a, b.w, acc.w);
    }
    *(float4*)(g_Mv + d * 4096 + c * 64 + g0 + cg) = acc;
}

// ---------------------------------------------------------------------------
// Kernel A: fused dual GEMM per 64-row tile on tensor cores.
//   xv   = (x*mask) @ Mv_deg -> g_xvh (fp16)
//   skip = (x*mask) @ Ws_deg -> g_skip (fp32)
// mma.sync.m16n8k8 tf32 with 3-term split (Xhi*Whi + Xhi*Wlo + Xlo*Whi):
// fp32-equivalent accuracy (~1e-7). Warp w: m-tile = w&3 (16 rows),
// n-half = w>>2 (32 cols = 4 n-tiles), both matrices.
// All fragment LDS are bank-conflict-free under ASTR=68 ((r*68+c)%32 spans all).
// ---------------------------------------------------------------------------
#define ASTR 68
__global__ __launch_bounds__(256) void kernelA(
    const float* __restrict__ x0, const float* __restrict__ x1, const float* __restrict__ x2,
    const float* __restrict__ mask,
    const float* __restrict__ Ws0, const float* __restrict__ Ws1, const float* __restrict__ Ws2)
{
    extern __shared__ __align__(16) float smem[];
    float* sX   = smem;                 // [64][ASTR] row r, col k
    float* sWmT = smem + 64 * ASTR;     // [64][ASTR] row c, col k (transposed)
    float* sWsT = smem + 2 * 64 * ASTR;

    int bx = blockIdx.x, tid = threadIdx.x;
    int tile, md, moff;
    const float *x, *Ws, *Wm;
    if (bx < 256)       { tile = bx;        x = x0; Ws = Ws0; Wm = g_Mv;        md = 1; moff = 0; }
    else if (bx < 1024) { tile = bx - 256;  x = x1; Ws = Ws1; Wm = g_Mv + 4096; md = 3; moff = 1; }
    else                { tile = bx - 1024; x = x2; Ws = Ws2; Wm = g_Mv + 8192; md = 5; moff = 4; }
    int row0 = tile * 64;

    // x tile with mask applied
    const float* xb = x + (size_t)row0 * 64;
    #pragma unroll
    for (int it = 0; it < 4; ++it) {
        int i = tid * 4 + it * 1024;
        int r = i >> 6, c = i & 63;
        float4 v = *(const float4*)(xb + i);
        float mk = mask[(row0 + r) / md];
        float* dst = sX + r * ASTR + c;
        dst[0] = v.x * mk; dst[1] = v.y * mk; dst[2] = v.z * mk; dst[3] = v.w * mk;
    }
    // Transposed weight loads
    #pragma unroll
    for (int it = 0; it < 16; ++it) {
        int i = tid + it * 256;
        int k = i >> 6, c = i & 63;
        sWmT[c * ASTR + k] = Wm[i];
        sWsT[c * ASTR + k] = Ws[i];
    }
    __syncthreads();

    int wp = tid >> 5, lane = tid & 31;
    int gid = lane >> 2, tig = lane & 3;
    int m0 = (wp & 3) * 16;         // 16-row m-tile
    int cq = (wp >> 2) * 32;        // 32-col n-half (4 n-tiles of 8)

    float accM[4][4], accS[4][4];
    #pragma unroll
    for (int nt = 0; nt < 4; ++nt)
        #pragma unroll
        for (int q = 0; q < 4; ++q) { accM[nt][q] = 0.f; accS[nt][q] = 0.f; }

    #pragma unroll
    for (int k0 = 0; k0 < 64; k0 += 8) {
        // A fragments (m16k8 tf32 layout), hi/lo split
        const float* xr0 = sX + (m0 + gid) * ASTR + k0;
        const float* xr1 = xr0 + 8 * ASTR;
        float f0 = xr0[tig], f1 = xr1[tig], f2 = xr0[tig + 4], f3 = xr1[tig + 4];
        uint32_t ah0 = f2tf(f0), ah1 = f2tf(f1), ah2 = f2tf(f2), ah3 = f2tf(f3);
        uint32_t al0 = f2tf(f0 - tf2f(ah0)), al1 = f2tf(f1 - tf2f(ah1));
        uint32_t al2 = f2tf(f2 - tf2f(ah2)), al3 = f2tf(f3 - tf2f(ah3));

        #pragma unroll
        for (int nt = 0; nt < 4; ++nt) {
            int c0 = cq + nt * 8;
            // B fragment rows (k-major in transposed tile): W[k][c] = WT[c*ASTR+k]
            const float* wmp = sWmT + (c0 + gid) * ASTR + k0;
            float bm0 = wmp[tig], bm1 = wmp[tig + 4];
            uint32_t bmh0 = f2tf(bm0), bmh1 = f2tf(bm1);
            uint32_t bml0 = f2tf(bm0 - tf2f(bmh0)), bml1 = f2tf(bm1 - tf2f(bmh1));
            MMA_TF32(accM[nt], ah0, ah1, ah2, ah3, bmh0, bmh1);
            MMA_TF32(accM[nt], ah0, ah1, ah2, ah3, bml0, bml1);
            MMA_TF32(accM[nt], al0, al1, al2, al3, bmh0, bmh1);

            const float* wsp = sWsT + (c0 + gid) * ASTR + k0;
            float bs0 = wsp[tig], bs1 = wsp[tig + 4];
            uint32_t bsh0 = f2tf(bs0), bsh1 = f2tf(bs1);
            uint32_t bsl0 = f2tf(bs0 - tf2f(bsh0)), bsl1 = f2tf(bs1 - tf2f(bsh1));
            MMA_TF32(accS[nt], ah0, ah1, ah2, ah3, bsh0, bsh1);
            MMA_TF32(accS[nt], ah0, ah1, ah2, ah3, bsl0, bsl1);
            MMA_TF32(accS[nt], al0, al1, al2, al3, bsh0, bsh1);
        }
    }

    // Epilogue: D frag rows are (m0+gid) and (m0+gid+8); cols 2*tig, 2*tig+1.
    int r0g = row0 + m0 + gid;
    int r1g = r0g + 8;
    int bn0 = r0g / md, bn1 = r1g / md;
    int base0 = (bn0 * 9 + moff + (r0g - bn0 * md)) * 64;
    int base1 = (bn1 * 9 + moff + (r1g - bn1 * md)) * 64;
    #pragma unroll
    for (int nt = 0; nt < 4; ++nt) {
        int col = cq + nt * 8 + 2 * tig;
        *(__half2*)(g_xvh + base0 + col) = __floats2half2_rn(accM[nt][0], accM[nt][1]);
        *(__half2*)(g_xvh + base1 + col) = __floats2half2_rn(accM[nt][2], accM[nt][3]);
        *(float2*)(g_skip + base0 + col) = make_float2(accS[nt][0], accS[nt][1]);
        *(float2*)(g_skip + base1 + col) = make_float2(accS[nt][2], accS[nt][3]);
    }
}

// ---------------------------------------------------------------------------
// Kernel B (R5 known-good): one block per point, 288 threads.
// ---------------------------------------------------------------------------
__global__ __launch_bounds__(288) void kernelB(
    const float* __restrict__ points, const int* __restrict__ pidx,
    const float* __restrict__ mask, float* __restrict__ out)
{
    __shared__ float sw[32];
    __shared__ int   srow[32];
    __shared__ int   snnz;
    __shared__ __align__(8) float vbuf[576];
    __shared__ __align__(8) float fbuf[192];

    int bn = blockIdx.x;
    int tid = threadIdx.x;

    if (tid < 32) {
        int idx  = pidx[bn * 32 + tid];
        int b    = bn >> 12;                 // N = 4096
        int prow = (b << 12) + idx;
        float cx = points[bn * 3 + 0], cy = points[bn * 3 + 1], cz = points[bn * 3 + 2];
        float dx = points[prow * 3 + 0] - cx;
        float dy = points[prow * 3 + 1] - cy;
        float dz = points[prow * 3 + 2] - cz;
        float r  = sqrtf(fmaf(dx, dx, fmaf(dy, dy, fmaf(dz, dz, 1e-12f))));
        float w  = 1.0f - r / 0.4f;
        bool act = w > 0.0f;
        unsigned bal = __ballot_sync(0xffffffffu, act);
        int pos = __popc(bal & ((1u << tid) - 1u));
        if (act) { sw[pos] = w; srow[pos] = prow * 576; }
        if (tid == 0) snnz = __popc(bal);
    }
    __syncthreads();

    int m = tid >> 5, j = tid & 31;
    int off = m * 64 + j * 2;
    int nnz = snnz;

    float ax = 0.f, ay = 0.f;
    int i = 0;
    for (; i + 4 <= nnz; i += 4) {
        float w0 = sw[i + 0], w1 = sw[i + 1], w2 = sw[i + 2], w3 = sw[i + 3];
        float2 p0 = __half22float2(*(const __half2*)(g_xvh + srow[i + 0] + off));
        float2 p1 = __half22float2(*(const __half2*)(g_xvh + srow[i + 1] + off));
        float2 p2 = __half22float2(*(const __half2*)(g_xvh + srow[i + 2] + off));
        float2 p3 = __half22float2(*(const __half2*)(g_xvh + srow[i + 3] + off));
        ax = fmaf(w0, p0.x, ax); ay = fmaf(w0, p0.y, ay);
        ax = fmaf(w1, p1.x, ax); ay = fmaf(w1, p1.y, ay);
        ax = fmaf(w2, p2.x, ax); ay = fmaf(w2, p2.y, ay);
        ax = fmaf(w3, p3.x, ax); ay = fmaf(w3, p3.y, ay);
    }
    for (; i < nnz; ++i) {
        float w0 = sw[i];
        float2 p0 = __half22float2(*(const __half2*)(g_xvh + srow[i] + off));
        ax = fmaf(w0, p0.x, ax); ay = fmaf(w0, p0.y, ay);
    }
    vbuf[off] = ax; vbuf[off + 1] = ay;
    __syncthreads();

    if (tid < 192) {
        int d  = tid >> 6, co = tid & 63;
        int m0 = (d == 0) ? 0 : (d == 1 ? 1 : 4);
        int mc = (d == 0) ? 1 : (d == 1 ? 3 : 5);
        float S = 0.f;
        for (int mm = 0; mm < mc; ++mm) {
            float v = vbuf[(m0 + mm) * 64 + co];
            S = fmaf(v, v, S);
        }
        float scale = rsqrtf(S + 0.01f);
        float f = scale;
        if (d > 0) {
            float S2 = S * scale * scale;             // = sum of normalized v^2
            float nn = sqrtf(S2 + 0.01f);
            f = scale * (1.0f / (1.0f + __expf(-nn)));
        }
        fbuf[tid] = f;
    }
    __syncthreads();

    float mk = mask[bn];
    int d = (m == 0) ? 0 : (m < 4 ? 1 : 2);
    float2 f2 = *(const float2*)&fbuf[d * 64 + 2 * j];
    float a0 = ax * f2.x, a1 = ay * f2.y;
    if (m == 0) { a0 = fmaxf(a0, 0.f); a1 = fmaxf(a1, 0.f); }

    float2 sk = *(const float2*)(g_skip + bn * 576 + off);
    float o0 = (a0 + sk.x) * mk;
    float o1 = (a1 + sk.y) * mk;

    float* op;
    if (m == 0)      op = out + bn * 64 + 2 * j;
    else if (m < 4)  op = out + OUT1_OFF + (bn * 3 + (m - 1)) * 64 + 2 * j;
    else             op = out + OUT2_OFF + (bn * 5 + (m - 4)) * 64 + 2 * j;
    *(float2*)op = make_float2(o0, o1);
}

// ---------------------------------------------------------------------------
extern "C" void kernel_launch(void* const* d_in, const int* in_sizes, int n_in,
                              void* d_out, int out_size) {
    const float* x0     = (const float*)d_in[0];
    const float* x1     = (const float*)d_in[1];
    const float* x2     = (const float*)d_in[2];
    const float* points = (const float*)d_in[3];
    const int*   pidx   = (const int*)  d_in[4];
    const float* mask   = (const float*)d_in[5];
    const float* Wc0    = (const float*)d_in[6];
    const float* Wc1    = (const float*)d_in[7];
    const float* Wc2    = (const float*)d_in[8];
    const float* Wv0    = (const float*)d_in[9];
    const float* Wv1    = (const float*)d_in[10];
    const float* Wv2    = (const float*)d_in[11];
    const float* Ws0    = (const float*)d_in[12];
    const float* Ws1    = (const float*)d_in[13];
    const float* Ws2    = (const float*)d_in[14];
    float* out = (float*)d_out;

    const int smemA = 3 * 64 * ASTR * sizeof(float);   // 52224 B
    cudaFuncSetAttribute(kernelA, cudaFuncAttributeMaxDynamicSharedMemorySize, smemA);

    kernelM<<<12, 256>>>(Wc0, Wc1, Wc2, Wv0, Wv1, Wv2);
    kernelA<<<2304, 256, smemA>>>(x0, x1, x2, mask, Ws0, Ws1, Ws2);
    kernelB<<<16384, 288>>>(points, pidx, mask, out);
}